// round 1
// baseline (speedup 1.0000x reference)
#include <cuda_runtime.h>
#include <cstdint>

#define D_MODEL 1024
#define SEQ     2048
#define BATCH   4
#define NHEAD   16
#define DHEAD   64
#define MTOT    (BATCH*SEQ)   // 8192
#define LN_EPS  1e-5f

// ---------------------------------------------------------------------------
// Scratch (no cudaMalloc allowed): 5 x 32MB fp32 buffers
// ---------------------------------------------------------------------------
__device__ float g_q[(size_t)MTOT * D_MODEL];
__device__ float g_k[(size_t)MTOT * D_MODEL];
__device__ float g_v[(size_t)MTOT * D_MODEL];
__device__ float g_attn[(size_t)MTOT * D_MODEL];
__device__ float g_x[(size_t)MTOT * D_MODEL];

// ---------------------------------------------------------------------------
// GEMM: C[M,N] = A[M,K] @ W[N,K]^T + bias[N]  (+ resid[M,N] if RESID)
// A row-major K-contiguous, W row-major K-contiguous (torch Linear weight).
// Tiles: 128x128x16, 256 threads, 8x8 micro-tile.
// Assumes M%128==0, N%128==0, K%16==0 (true here: 8192,1024,1024).
// ---------------------------------------------------------------------------
template<bool RESID>
__global__ __launch_bounds__(256)
void gemm_bias_kernel(const float* __restrict__ A,
                      const float* __restrict__ W,
                      const float* __restrict__ bias,
                      const float* __restrict__ resid,
                      float* __restrict__ C,
                      int M, int N, int K)
{
    __shared__ float As[16][128];   // [k][m]
    __shared__ float Bs[16][128];   // [k][n]

    const int tid = threadIdx.x;
    const int tx  = tid & 15;       // 0..15 -> n direction
    const int ty  = tid >> 4;       // 0..15 -> m direction
    const int m0  = blockIdx.y * 128;
    const int n0  = blockIdx.x * 128;

    float acc[8][8];
#pragma unroll
    for (int i = 0; i < 8; i++)
#pragma unroll
        for (int j = 0; j < 8; j++) acc[i][j] = 0.0f;

    for (int kt = 0; kt < K; kt += 16) {
        // Load A tile (128x16) and B tile (128x16), transposed into smem.
        // 512 float4 per tile, 2 per thread.
#pragma unroll
        for (int q = 0; q < 2; q++) {
            int id  = tid + q * 256;          // 0..511
            int row = id >> 2;                // 0..127
            int c4  = (id & 3) * 4;           // 0,4,8,12
            float4 fa = *(const float4*)(A + (size_t)(m0 + row) * K + kt + c4);
            As[c4 + 0][row] = fa.x;
            As[c4 + 1][row] = fa.y;
            As[c4 + 2][row] = fa.z;
            As[c4 + 3][row] = fa.w;
            float4 fb = *(const float4*)(W + (size_t)(n0 + row) * K + kt + c4);
            Bs[c4 + 0][row] = fb.x;
            Bs[c4 + 1][row] = fb.y;
            Bs[c4 + 2][row] = fb.z;
            Bs[c4 + 3][row] = fb.w;
        }
        __syncthreads();

#pragma unroll
        for (int k = 0; k < 16; k++) {
            float4 a0 = *(const float4*)&As[k][ty * 8];
            float4 a1 = *(const float4*)&As[k][ty * 8 + 4];
            float4 b0 = *(const float4*)&Bs[k][tx * 8];
            float4 b1 = *(const float4*)&Bs[k][tx * 8 + 4];
            float av[8] = {a0.x, a0.y, a0.z, a0.w, a1.x, a1.y, a1.z, a1.w};
            float bv[8] = {b0.x, b0.y, b0.z, b0.w, b1.x, b1.y, b1.z, b1.w};
#pragma unroll
            for (int i = 0; i < 8; i++)
#pragma unroll
                for (int j = 0; j < 8; j++)
                    acc[i][j] += av[i] * bv[j];
        }
        __syncthreads();
    }

    // Epilogue
#pragma unroll
    for (int i = 0; i < 8; i++) {
        int m = m0 + ty * 8 + i;
#pragma unroll
        for (int j = 0; j < 8; j++) {
            int n = n0 + tx * 8 + j;
            float c = acc[i][j] + bias[n];
            if (RESID) c += resid[(size_t)m * N + n];
            C[(size_t)m * N + n] = c;
        }
    }
}

// ---------------------------------------------------------------------------
// Flash attention (fp32, online softmax).
// grid = (SEQ/64, NHEAD, BATCH), 256 threads (8 warps).
// Each warp owns 8 query rows; each lane owns cols {lane, lane+32} of O/S.
// smem = sQ(16K) + sKV(16K, reused for K^T then V) + sP(16K) = 48KB exactly.
// ---------------------------------------------------------------------------
__global__ __launch_bounds__(256)
void attn_kernel(const float* __restrict__ Q,
                 const float* __restrict__ Kg,
                 const float* __restrict__ Vg,
                 float* __restrict__ Og)
{
    __shared__ float sQ[64][64];    // [row][d]
    __shared__ float sKV[64][64];   // K phase: [d][c] ; V phase: [c][d]
    __shared__ float sP[64][64];    // [row][c]

    const int qt   = blockIdx.x;
    const int h    = blockIdx.y;
    const int b    = blockIdx.z;
    const int tid  = threadIdx.x;
    const int warp = tid >> 5;
    const int lane = tid & 31;

    const size_t base = ((size_t)b * SEQ) * D_MODEL + (size_t)h * DHEAD;

    // Load Q tile (64 rows x 64 d), 1024 float4, 4 per thread
    for (int i = tid; i < 1024; i += 256) {
        int r  = i >> 4;
        int c4 = (i & 15) * 4;
        float4 f = *(const float4*)(Q + base + (size_t)(qt * 64 + r) * D_MODEL + c4);
        *(float4*)&sQ[r][c4] = f;
    }

    float m[8], l[8], acc0[8], acc1[8];
#pragma unroll
    for (int r = 0; r < 8; r++) {
        m[r] = -1e30f; l[r] = 0.0f; acc0[r] = 0.0f; acc1[r] = 0.0f;
    }

    const float scale = 0.125f;  // 1/sqrt(64)

    for (int kt = 0; kt < SEQ / 64; kt++) {
        __syncthreads();  // previous PV phase done reading sKV (also covers sQ 1st iter)
        // Load K tile transposed: sKV[d][c] = K[kt*64+c][d]
        for (int i = tid; i < 1024; i += 256) {
            int r  = i >> 4;          // key index within tile
            int c4 = (i & 15) * 4;    // d offset
            float4 f = *(const float4*)(Kg + base + (size_t)(kt * 64 + r) * D_MODEL + c4);
            sKV[c4 + 0][r] = f.x;
            sKV[c4 + 1][r] = f.y;
            sKV[c4 + 2][r] = f.z;
            sKV[c4 + 3][r] = f.w;
        }
        __syncthreads();

        // Scores: s[r][c] for c = lane, lane+32
        float s0[8], s1[8];
#pragma unroll
        for (int r = 0; r < 8; r++) { s0[r] = 0.0f; s1[r] = 0.0f; }
#pragma unroll 4
        for (int d = 0; d < 64; d++) {
            float k0 = sKV[d][lane];
            float k1 = sKV[d][lane + 32];
#pragma unroll
            for (int r = 0; r < 8; r++) {
                float qv = sQ[warp * 8 + r][d];
                s0[r] += qv * k0;
                s1[r] += qv * k1;
            }
        }

        // Online softmax update per row
#pragma unroll
        for (int r = 0; r < 8; r++) {
            float a = s0[r] * scale;
            float c = s1[r] * scale;
            float tmax = fmaxf(a, c);
#pragma unroll
            for (int o = 16; o > 0; o >>= 1)
                tmax = fmaxf(tmax, __shfl_xor_sync(0xffffffffu, tmax, o));
            float newm = fmaxf(m[r], tmax);
            float e0 = __expf(a - newm);
            float e1 = __expf(c - newm);
            float ts = e0 + e1;
#pragma unroll
            for (int o = 16; o > 0; o >>= 1)
                ts += __shfl_xor_sync(0xffffffffu, ts, o);
            float alpha = __expf(m[r] - newm);
            l[r] = l[r] * alpha + ts;
            m[r] = newm;
            acc0[r] *= alpha;
            acc1[r] *= alpha;
            sP[warp * 8 + r][lane]      = e0;
            sP[warp * 8 + r][lane + 32] = e1;
        }
        __syncthreads();  // all warps done reading K, sP written

        // Load V tile: sKV[c][d] = V[kt*64+c][d]
        for (int i = tid; i < 1024; i += 256) {
            int r  = i >> 4;
            int c4 = (i & 15) * 4;
            float4 f = *(const float4*)(Vg + base + (size_t)(kt * 64 + r) * D_MODEL + c4);
            *(float4*)&sKV[r][c4] = f;
        }
        __syncthreads();

        // O += P @ V : acc0 -> d=lane, acc1 -> d=lane+32
#pragma unroll 4
        for (int c = 0; c < 64; c++) {
            float v0 = sKV[c][lane];
            float v1 = sKV[c][lane + 32];
#pragma unroll
            for (int r = 0; r < 8; r++) {
                float p = sP[warp * 8 + r][c];
                acc0[r] += p * v0;
                acc1[r] += p * v1;
            }
        }
    }

    // Write normalized output
#pragma unroll
    for (int r = 0; r < 8; r++) {
        int row = warp * 8 + r;
        float inv = 1.0f / l[r];
        size_t o = base + (size_t)(qt * 64 + row) * D_MODEL;
        Og[o + lane]      = acc0[r] * inv;
        Og[o + lane + 32] = acc1[r] * inv;
    }
}

// ---------------------------------------------------------------------------
// LayerNorm: one block per row (1024 elems), 256 threads (4 elems each).
// ---------------------------------------------------------------------------
__global__ __launch_bounds__(256)
void ln_kernel(const float* __restrict__ X,
               const float* __restrict__ gamma,
               const float* __restrict__ beta,
               float* __restrict__ out)
{
    const int row = blockIdx.x;
    const int tid = threadIdx.x;
    const float* x = X + (size_t)row * D_MODEL;

    float4 f = *(const float4*)(x + tid * 4);
    float s  = f.x + f.y + f.z + f.w;
    float ss = f.x * f.x + f.y * f.y + f.z * f.z + f.w * f.w;

#pragma unroll
    for (int o = 16; o > 0; o >>= 1) {
        s  += __shfl_xor_sync(0xffffffffu, s,  o);
        ss += __shfl_xor_sync(0xffffffffu, ss, o);
    }

    __shared__ float sh[16];
    const int warp = tid >> 5, lane = tid & 31;
    if (lane == 0) { sh[warp] = s; sh[warp + 8] = ss; }
    __syncthreads();
    if (tid == 0) {
        float S = 0.0f, SS = 0.0f;
#pragma unroll
        for (int w = 0; w < 8; w++) { S += sh[w]; SS += sh[w + 8]; }
        float mu  = S * (1.0f / D_MODEL);
        float var = SS * (1.0f / D_MODEL) - mu * mu;
        sh[0] = mu;
        sh[1] = rsqrtf(var + LN_EPS);
    }
    __syncthreads();
    float mu = sh[0], rstd = sh[1];

    float4 gm = *(const float4*)(gamma + tid * 4);
    float4 bt = *(const float4*)(beta  + tid * 4);
    float4 o4;
    o4.x = (f.x - mu) * rstd * gm.x + bt.x;
    o4.y = (f.y - mu) * rstd * gm.y + bt.y;
    o4.z = (f.z - mu) * rstd * gm.z + bt.z;
    o4.w = (f.w - mu) * rstd * gm.w + bt.w;
    *(float4*)(out + (size_t)row * D_MODEL + tid * 4) = o4;
}

// ---------------------------------------------------------------------------
// Launch
// ---------------------------------------------------------------------------
extern "C" void kernel_launch(void* const* d_in, const int* in_sizes, int n_in,
                              void* d_out, int out_size)
{
    const float* batch = (const float*)d_in[0];
    const float* wq    = (const float*)d_in[1];
    const float* bq    = (const float*)d_in[2];
    const float* wk    = (const float*)d_in[3];
    const float* bk    = (const float*)d_in[4];
    const float* wv    = (const float*)d_in[5];
    const float* bv    = (const float*)d_in[6];
    const float* wo    = (const float*)d_in[7];
    const float* bo    = (const float*)d_in[8];
    const float* ln_g  = (const float*)d_in[9];
    const float* ln_b  = (const float*)d_in[10];

    float *q, *k, *v, *attn, *x;
    cudaGetSymbolAddress((void**)&q,    g_q);
    cudaGetSymbolAddress((void**)&k,    g_k);
    cudaGetSymbolAddress((void**)&v,    g_v);
    cudaGetSymbolAddress((void**)&attn, g_attn);
    cudaGetSymbolAddress((void**)&x,    g_x);

    dim3 gg(D_MODEL / 128, MTOT / 128);  // (8, 64)
    gemm_bias_kernel<false><<<gg, 256>>>(batch, wq, bq, nullptr, q, MTOT, D_MODEL, D_MODEL);
    gemm_bias_kernel<false><<<gg, 256>>>(batch, wk, bk, nullptr, k, MTOT, D_MODEL, D_MODEL);
    gemm_bias_kernel<false><<<gg, 256>>>(batch, wv, bv, nullptr, v, MTOT, D_MODEL, D_MODEL);

    dim3 ga(SEQ / 64, NHEAD, BATCH);     // (32, 16, 4)
    attn_kernel<<<ga, 256>>>(q, k, v, attn);

    gemm_bias_kernel<true><<<gg, 256>>>(attn, wo, bo, batch, x, MTOT, D_MODEL, D_MODEL);

    ln_kernel<<<MTOT, 256>>>(x, ln_g, ln_b, (float*)d_out);
}